// round 6
// baseline (speedup 1.0000x reference)
#include <cuda_runtime.h>

#define Nn 2048
#define Ee 4096
#define MDV 32
#define MDE 32
#define NB 148
#define NT 512
#define GSTRIDE (NB * NT)

#define TN4 (Nn * Ee / 4)
#define VN4 (Nn * Nn / 4)
#define EN4 (Ee * Ee / 4)

// ---------------- static device state ----------------
static __device__ int      g_en[Ee * 2];        // edge endpoints (a,b)
static __device__ int      g_ecnt[Ee];          // T-scan slot counter
static __device__ int      g_vcnt[Nn];          // adj_v padded-row counts
static __device__ float    g_vdiag[Nn];
static __device__ int      g_vcol[Nn * MDV];
static __device__ float    g_vvalp[Nn * MDV];
static __device__ float    g_msum[Nn * MDV];    // mult1 accum per entry
static __device__ int      g_ecnt2[Ee];         // adj_e padded-row counts
static __device__ float    g_ediag[Ee];
static __device__ int      g_ecol[Ee * MDE];
static __device__ float    g_evalp[Ee * MDE];
static __device__ float    g_aval[Ee * MDE];
static __device__ unsigned g_colmax[Ee];
static __device__ int      g_map0[Ee];          // edge -> adj_v entry (a,b)
static __device__ int      g_map1[Ee];          // edge -> adj_v entry (b,a)
static __device__ float    g_X1F1[Nn * 256];
static __device__ float    g_HWn[Nn * 128];     // HW1/HW3/HW5
static __device__ float    g_X3[Nn * 128];
static __device__ float    g_Z2F2[Ee * 32];
static __device__ float    g_HWe[Ee * 16];      // HW2/HW4
static __device__ float    g_Z4[Ee * 16];
static __device__ float    g_s[Ee];             // gates s1..s5
static __device__ unsigned g_barArr;
static __device__ unsigned g_barGen;

// ---------------- helpers ----------------
__device__ __forceinline__ unsigned f2ord(float f) {
    unsigned u = __float_as_uint(f);
    return (u & 0x80000000u) ? ~u : (u | 0x80000000u);
}
__device__ __forceinline__ float ord2f(unsigned u) {
    return __uint_as_float((u & 0x80000000u) ? (u & 0x7fffffffu) : ~u);
}

// software grid barrier: all NB blocks guaranteed co-resident (1/SM)
__device__ __forceinline__ void gbar() {
    __syncthreads();
    if (threadIdx.x == 0) {
        unsigned gen = *((volatile unsigned*)&g_barGen);
        __threadfence();
        unsigned t = atomicAdd(&g_barArr, 1u);
        if (t == NB - 1) {
            atomicExch(&g_barArr, 0u);
            __threadfence();
            atomicAdd(&g_barGen, 1u);
        } else {
            while (*((volatile unsigned*)&g_barGen) == gen) __nanosleep(32);
        }
    }
    __syncthreads();
}

// ---------------- phase bodies ----------------
__device__ void ph_clear() {
    for (int i = blockIdx.x * NT + threadIdx.x; i < Nn * MDV; i += GSTRIDE) {
        g_msum[i] = 0.f;
        if (i < Ee) { g_ecnt[i] = 0; g_ecnt2[i] = 0; }
        if (i < Nn) g_vcnt[i] = 0;
    }
}

__device__ void ph_scan(const float4* __restrict__ T, const float4* __restrict__ AV,
                        const float4* __restrict__ AE) {
    int g0 = blockIdx.x * NT + threadIdx.x;
    // T scan
    #pragma unroll 4
    for (int idx = g0; idx < TN4; idx += GSTRIDE) {
        float4 v = T[idx];
        int base = idx * 4;
        int i = base >> 12;         // /Ee
        int e0 = base & (Ee - 1);
        float vals[4] = {v.x, v.y, v.z, v.w};
        #pragma unroll
        for (int l = 0; l < 4; l++) {
            float val = vals[l];
            if (val != 0.f) {
                int e = e0 + l;
                int k = (int)(val + 0.5f);
                int slot = atomicAdd(&g_ecnt[e], k);
                if (slot < 2) {
                    g_en[e * 2 + slot] = i;
                    if (k == 2) g_en[e * 2 + 1] = i;
                }
            }
        }
    }
    // adj_v scan
    #pragma unroll 4
    for (int idx = g0; idx < VN4; idx += GSTRIDE) {
        float4 v = AV[idx];
        int base = idx * 4;
        int i = base >> 11;         // /Nn
        int j0 = base & (Nn - 1);
        float vals[4] = {v.x, v.y, v.z, v.w};
        #pragma unroll
        for (int l = 0; l < 4; l++) {
            float val = vals[l];
            if (val != 0.f) {
                int j = j0 + l;
                if (i == j) g_vdiag[i] = val;
                else {
                    int slot = atomicAdd(&g_vcnt[i], 1);
                    if (slot < MDV) {
                        g_vcol[i * MDV + slot] = j;
                        g_vvalp[i * MDV + slot] = val;
                    }
                }
            }
        }
    }
    // adj_e scan
    #pragma unroll 4
    for (int idx = g0; idx < EN4; idx += GSTRIDE) {
        float4 v = AE[idx];
        int base = idx * 4;
        int e = base >> 12;         // /Ee
        int f0 = base & (Ee - 1);
        float vals[4] = {v.x, v.y, v.z, v.w};
        #pragma unroll
        for (int l = 0; l < 4; l++) {
            float val = vals[l];
            if (val != 0.f) {
                int f = f0 + l;
                if (e == f) g_ediag[e] = val;
                else {
                    int slot = atomicAdd(&g_ecnt2[e], 1);
                    if (slot < MDE) {
                        g_ecol[e * MDE + slot] = f;
                        g_evalp[e * MDE + slot] = val;
                    }
                }
            }
        }
    }
}

__device__ __forceinline__ int find_entry(int row, int col) {
    int cnt = g_vcnt[row]; if (cnt > MDV) cnt = MDV;
    for (int s = 0; s < cnt; s++)
        if (g_vcol[row * MDV + s] == col) return row * MDV + s;
    return -1;
}
__device__ void ph_map() {
    for (int e = blockIdx.x * NT + threadIdx.x; e < Ee; e += GSTRIDE) {
        int a = g_en[2 * e], b = g_en[2 * e + 1];
        if (a > b) { int t = a; a = b; b = t; g_en[2 * e] = a; g_en[2 * e + 1] = b; }
        if (a == b) { g_map0[e] = -1; g_map1[e] = -1; continue; }
        g_map0[e] = find_entry(a, b);
        g_map1[e] = find_entry(b, a);
    }
}

__device__ void ph_dot(const float* __restrict__ A, int lda, int K,
                       const float* __restrict__ p, int R) {
    int w0 = blockIdx.x * (NT / 32) + (threadIdx.x >> 5);
    int lane = threadIdx.x & 31;
    for (int r = w0; r < R; r += NB * (NT / 32)) {
        float acc = 0.f;
        for (int k = lane; k < K; k += 32) acc += A[r * lda + k] * p[k];
        #pragma unroll
        for (int o = 16; o > 0; o >>= 1) acc += __shfl_xor_sync(0xffffffffu, acc, o);
        if (lane == 0) g_s[r] = acc;
    }
}

// 128-col GEMM on node rows (R=Nn), 4 subgroups of 128 threads per block
__device__ void ph_gemm128(const float* __restrict__ A, int lda, int K,
                           const float* __restrict__ B, float* __restrict__ out,
                           int ldc, int ocol, int fuse_ln,
                           const float* __restrict__ g, const float* __restrict__ be,
                           float* shAs, float* shRed, int R) {
    int sub = threadIdx.x >> 7;
    int c = threadIdx.x & 127;
    int w = c >> 5, lane = c & 31;
    float* As = shAs + sub * 256;
    const int ngrp = NB * 4;
    int trips = (R + ngrp - 1) / ngrp;
    for (int t = 0; t < trips; t++) {
        int r = t * ngrp + blockIdx.x * 4 + sub;
        bool act = r < R;
        __syncthreads();
        if (act) for (int k = c; k < K; k += 128) As[k] = A[r * lda + k];
        __syncthreads();
        float acc = 0.f;
        if (act) {
            #pragma unroll 8
            for (int k = 0; k < K; k++) acc += As[k] * B[k * 128 + c];
        }
        if (fuse_ln) {
            float v = acc;
            #pragma unroll
            for (int o = 16; o > 0; o >>= 1) v += __shfl_xor_sync(0xffffffffu, v, o);
            if (lane == 0) shRed[sub * 4 + w] = v;
            __syncthreads();
            float mean = (shRed[sub * 4] + shRed[sub * 4 + 1] +
                          shRed[sub * 4 + 2] + shRed[sub * 4 + 3]) * (1.f / 128.f);
            __syncthreads();
            float d = acc - mean;
            v = d * d;
            #pragma unroll
            for (int o = 16; o > 0; o >>= 1) v += __shfl_xor_sync(0xffffffffu, v, o);
            if (lane == 0) shRed[sub * 4 + w] = v;
            __syncthreads();
            float var = (shRed[sub * 4] + shRed[sub * 4 + 1] +
                         shRed[sub * 4 + 2] + shRed[sub * 4 + 3]) * (1.f / 128.f);
            __syncthreads();
            acc = fmaxf(d * rsqrtf(var + 1e-5f) * g[c] + be[c], 0.f);
        }
        if (act) out[r * ldc + ocol + c] = acc;
    }
}

// 16-col GEMM on edge rows (R=Ee), 32 row-groups of 16 threads per block
__device__ void ph_gemm16(const float* __restrict__ A, int lda, int K,
                          const float* __restrict__ B, float* __restrict__ out,
                          int ldc, int ocol, int reluA, int fuse_ln,
                          const float* __restrict__ g, const float* __restrict__ be,
                          float* shAsf, int R) {
    float (*As)[32] = (float (*)[32])shAsf;
    int rg = threadIdx.x >> 4, c = threadIdx.x & 15;
    const int nrows = NB * 32;
    int trips = (R + nrows - 1) / nrows;
    for (int t = 0; t < trips; t++) {
        int r = t * nrows + blockIdx.x * 32 + rg;
        bool act = r < R;
        __syncthreads();
        if (act) for (int k = c; k < K; k += 16) {
            float v = A[r * lda + k];
            if (reluA) v = fmaxf(v, 0.f);
            As[rg][k] = v;
        }
        __syncthreads();
        float acc = 0.f;
        if (act) {
            #pragma unroll 8
            for (int k = 0; k < K; k++) acc += As[rg][k] * B[k * 16 + c];
        }
        if (fuse_ln) {
            float s = acc;
            #pragma unroll
            for (int o = 8; o > 0; o >>= 1) s += __shfl_xor_sync(0xffffffffu, s, o, 16);
            float mean = s * (1.f / 16.f);
            float d = acc - mean;
            float s2 = d * d;
            #pragma unroll
            for (int o = 8; o > 0; o >>= 1) s2 += __shfl_xor_sync(0xffffffffu, s2, o, 16);
            float var = s2 * (1.f / 16.f);
            acc = fmaxf(d * rsqrtf(var + 1e-5f) * g[c] + be[c], 0.f);
        }
        if (act) out[r * ldc + ocol + c] = acc;
    }
}

__device__ void ph_scatter() {
    for (int e = blockIdx.x * NT + threadIdx.x; e < Ee; e += GSTRIDE) {
        int a = g_en[2 * e], b = g_en[2 * e + 1];
        if (a == b) continue;
        float sv = g_s[e];
        int m0 = g_map0[e]; if (m0 >= 0) atomicAdd(&g_msum[m0], sv);
        int m1 = g_map1[e]; if (m1 >= 0) atomicAdd(&g_msum[m1], sv);
    }
}

__device__ void ph_gather_node(const float* __restrict__ bias, float* __restrict__ out,
                               int ldc, int relu) {
    for (int v = blockIdx.x * NT + threadIdx.x; v < Nn * 128; v += GSTRIDE) {
        int i = v >> 7, c = v & 127;
        float acc = bias[c] + g_vdiag[i] * g_HWn[i * 128 + c];
        int cnt = g_vcnt[i]; if (cnt > MDV) cnt = MDV;
        for (int s = 0; s < cnt; s++) {
            int id = i * MDV + s;
            acc += g_msum[id] * g_vvalp[id] * g_HWn[g_vcol[id] * 128 + c];
        }
        if (relu) acc = fmaxf(acc, 0.f);
        out[i * ldc + c] = acc;
    }
}

__device__ void ph_colmax_seed() {
    for (int f = blockIdx.x * NT + threadIdx.x; f < Ee; f += GSTRIDE)
        g_colmax[f] = f2ord(g_ediag[f]);
}
__device__ void ph_msum_clear() {
    for (int i = blockIdx.x * NT + threadIdx.x; i < Nn * MDV; i += GSTRIDE)
        g_msum[i] = 0.f;
}

__device__ void ph_entries() {
    for (int e = blockIdx.x * NT + threadIdx.x; e < Ee; e += GSTRIDE) {
        int a0 = g_en[2 * e], a1 = g_en[2 * e + 1];
        float sa0 = g_s[a0], sa1 = g_s[a1];
        int cnt = g_ecnt2[e]; if (cnt > MDE) cnt = MDE;
        for (int s = 0; s < cnt; s++) {
            int id = e * MDE + s;
            int f = g_ecol[id];
            int b0 = g_en[2 * f], b1 = g_en[2 * f + 1];
            float m = sa0 * ((float)(a0 == b0) + (float)(a0 == b1))
                    + sa1 * ((float)(a1 == b0) + (float)(a1 == b1));
            float av = m * g_evalp[id];
            g_aval[id] = av;
            atomicMax(&g_colmax[f], f2ord(av));
        }
    }
}

__device__ void ph_gather_edge(const float* __restrict__ bias, float* __restrict__ out,
                               int ldc, int relu) {
    for (int v = blockIdx.x * NT + threadIdx.x; v < Ee * 16; v += GSTRIDE) {
        int e = v >> 4, c = v & 15;
        float acc = bias[c] + g_ediag[e] * (1.f / ord2f(g_colmax[e])) * g_HWe[e * 16 + c];
        int cnt = g_ecnt2[e]; if (cnt > MDE) cnt = MDE;
        for (int s = 0; s < cnt; s++) {
            int id = e * MDE + s;
            int f = g_ecol[id];
            acc += g_aval[id] * (1.f / ord2f(g_colmax[f])) * g_HWe[f * 16 + c];
        }
        if (relu) acc = fmaxf(acc, 0.f);
        out[e * ldc + c] = acc;
    }
}

// ---------------- the whole network in one persistent kernel ----------------
__global__ void __launch_bounds__(NT) k_all(
    const float* __restrict__ X, const float* __restrict__ Z,
    const float* __restrict__ adj_e, const float* __restrict__ adj_v,
    const float* __restrict__ T,
    const float* __restrict__ W1, const float* __restrict__ p1, const float* __restrict__ b1,
    const float* __restrict__ Wf1, const float* __restrict__ g1, const float* __restrict__ be1,
    const float* __restrict__ W2, const float* __restrict__ p2, const float* __restrict__ b2,
    const float* __restrict__ Wf2, const float* __restrict__ g2, const float* __restrict__ be2,
    const float* __restrict__ W3, const float* __restrict__ p3, const float* __restrict__ b3,
    const float* __restrict__ W4, const float* __restrict__ p4, const float* __restrict__ b4,
    const float* __restrict__ W5, const float* __restrict__ p5, const float* __restrict__ b5,
    float* __restrict__ out)
{
    __shared__ float shAs[1024];
    __shared__ float shRed[16];

    // P0: clear counters/msum
    ph_clear();
    gbar();
    // P1: fused sparse scan of T, adj_v, adj_e
    ph_scan((const float4*)T, (const float4*)adj_v, (const float4*)adj_e);
    gbar();
    // P2: map + s1 + HW1 + F1(LN) + F2(LN)   (all independent)
    ph_map();
    ph_dot(Z, 16, 16, p1, Ee);                                        // s1
    ph_gemm128(X, 64, 64, W1, g_HWn, 128, 0, 0, 0, 0, shAs, shRed, Nn);     // HW1
    ph_gemm128(X, 64, 64, Wf1, g_X1F1, 256, 128, 1, g1, be1, shAs, shRed, Nn); // F1
    ph_gemm16(Z, 16, 16, Wf2, g_Z2F2, 32, 16, 0, 1, g2, be2, shAs, Ee);     // F2
    gbar();
    // P3: scatter s1 into msum
    ph_scatter();
    gbar();
    // P4: gather -> X1 (relu) into X1F1[:, :128]
    ph_gather_node(b1, g_X1F1, 256, 1);
    gbar();
    // P5: s2 + HW2 + colmax seed + msum clear + HW3
    ph_dot(g_X1F1, 256, 256, p2, Nn);                                 // s2
    ph_gemm16(Z, 16, 16, W2, g_HWe, 16, 0, 1, 0, 0, 0, shAs, Ee);     // relu(Z)@W2
    ph_colmax_seed();
    ph_msum_clear();
    ph_gemm128(g_X1F1, 256, 256, W3, g_HWn, 128, 0, 0, 0, 0, shAs, shRed, Nn); // HW3
    gbar();
    // P6: edge entries (aval + colmax)
    ph_entries();
    gbar();
    // P7: gather edge -> Z2 (relu) into Z2F2[:, :16]
    ph_gather_edge(b2, g_Z2F2, 32, 1);
    gbar();
    // P8: s3 + HW4 + colmax re-seed (for gc4)
    ph_dot(g_Z2F2, 32, 32, p3, Ee);                                   // s3
    ph_gemm16(g_Z2F2, 32, 32, W4, g_HWe, 16, 0, 0, 0, 0, 0, shAs, Ee);// HW4
    ph_colmax_seed();
    gbar();
    // P9: scatter s3
    ph_scatter();
    gbar();
    // P10: gather -> X3 (relu)
    ph_gather_node(b3, g_X3, 128, 1);
    gbar();
    // P11: s4 + msum clear (for gc5)
    ph_dot(g_X3, 128, 128, p4, Nn);                                   // s4
    ph_msum_clear();
    gbar();
    // P12: edge entries
    ph_entries();
    gbar();
    // P13: gather edge -> Z4 (relu)
    ph_gather_edge(b4, g_Z4, 16, 1);
    gbar();
    // P14: s5 + HW5
    ph_dot(g_Z4, 16, 16, p5, Ee);                                     // s5
    ph_gemm128(g_X3, 128, 128, W5, g_HWn, 128, 0, 0, 0, 0, shAs, shRed, Nn); // HW5
    gbar();
    // P15: scatter s5
    ph_scatter();
    gbar();
    // P16: gather -> out (no relu)
    ph_gather_node(b5, out, 128, 0);
}

// ---------------- host launcher ----------------
extern "C" void kernel_launch(void* const* d_in, const int* in_sizes, int n_in,
                              void* d_out, int out_size) {
    (void)in_sizes; (void)n_in; (void)out_size;
    k_all<<<NB, NT>>>(
        (const float*)d_in[0], (const float*)d_in[1], (const float*)d_in[2],
        (const float*)d_in[3], (const float*)d_in[4],
        (const float*)d_in[5], (const float*)d_in[6], (const float*)d_in[7],
        (const float*)d_in[8], (const float*)d_in[9], (const float*)d_in[10],
        (const float*)d_in[11], (const float*)d_in[12], (const float*)d_in[13],
        (const float*)d_in[14], (const float*)d_in[15], (const float*)d_in[16],
        (const float*)d_in[17], (const float*)d_in[18], (const float*)d_in[19],
        (const float*)d_in[20], (const float*)d_in[21], (const float*)d_in[22],
        (const float*)d_in[23], (const float*)d_in[24], (const float*)d_in[25],
        (float*)d_out);
}

// round 7
// speedup vs baseline: 1.2387x; 1.2387x over previous
#include <cuda_runtime.h>

#define Nn 2048
#define Ee 4096
#define MDV 32
#define MDE 32
#define NB 148
#define NT 1024
#define GSTRIDE (NB * NT)

#define TN4 (Nn * Ee / 4)
#define VN4 (Nn * Nn / 4)
#define EN4 (Ee * Ee / 4)

// ---------------- static device state ----------------
static __device__ int      g_en[Ee * 2];        // edge endpoints (a,b)
static __device__ int      g_ecnt[Ee];          // T-scan slot counter
static __device__ int      g_vcnt[Nn];          // adj_v padded-row counts
static __device__ float    g_vdiag[Nn];
static __device__ int      g_vcol[Nn * MDV];
static __device__ float    g_vvalp[Nn * MDV];
static __device__ float    g_msum[Nn * MDV];    // mult1 accum per entry
static __device__ int      g_ecnt2[Ee];         // adj_e padded-row counts
static __device__ float    g_ediag[Ee];
static __device__ int      g_ecol[Ee * MDE];
static __device__ float    g_evalp[Ee * MDE];
static __device__ float    g_aval[Ee * MDE];
static __device__ unsigned g_colmax[Ee];
static __device__ int      g_map0[Ee];          // edge -> adj_v entry (a,b)
static __device__ int      g_map1[Ee];          // edge -> adj_v entry (b,a)
static __device__ float    g_X1F1[Nn * 256];
static __device__ float    g_HWn[Nn * 128];     // HW1/HW3/HW5
static __device__ float    g_X3[Nn * 128];
static __device__ float    g_Z2F2[Ee * 32];
static __device__ float    g_HWe[Ee * 16];      // HW2/HW4
static __device__ float    g_Z4[Ee * 16];
static __device__ float    g_s[Ee];             // gates s1..s5
static __device__ unsigned g_barArr;
static __device__ unsigned g_barGen;

// ---------------- helpers ----------------
__device__ __forceinline__ unsigned f2ord(float f) {
    unsigned u = __float_as_uint(f);
    return (u & 0x80000000u) ? ~u : (u | 0x80000000u);
}
__device__ __forceinline__ float ord2f(unsigned u) {
    return __uint_as_float((u & 0x80000000u) ? (u & 0x7fffffffu) : ~u);
}

// software grid barrier: 148 blocks, 1 per SM, guaranteed co-resident
__device__ __forceinline__ void gbar() {
    __syncthreads();
    if (threadIdx.x == 0) {
        unsigned gen = *((volatile unsigned*)&g_barGen);
        __threadfence();
        unsigned t = atomicAdd(&g_barArr, 1u);
        if (t == NB - 1) {
            atomicExch(&g_barArr, 0u);
            __threadfence();
            atomicAdd(&g_barGen, 1u);
        } else {
            while (*((volatile unsigned*)&g_barGen) == gen) __nanosleep(32);
        }
    }
    __syncthreads();
}

// ---------------- standalone kernels (full-occupancy scan path) ----------------
__global__ void k_clear() {
    int i = blockIdx.x * 256 + threadIdx.x;
    if (i < Nn * MDV) g_msum[i] = 0.f;
    if (i < Ee) { g_ecnt[i] = 0; g_ecnt2[i] = 0; }
    if (i < Nn) g_vcnt[i] = 0;
}

// fused single-pass scan of T, adj_v, adj_e (big grid, full occupancy)
__global__ void k_scan(const float4* __restrict__ T, const float4* __restrict__ AV,
                       const float4* __restrict__ AE) {
    int idx = blockIdx.x * 256 + threadIdx.x;
    if (idx < TN4) {
        float4 v = T[idx];
        int base = idx * 4;
        int i = base >> 12;         // /Ee
        int e0 = base & (Ee - 1);
        float vals[4] = {v.x, v.y, v.z, v.w};
        #pragma unroll
        for (int l = 0; l < 4; l++) {
            float val = vals[l];
            if (val != 0.f) {
                int e = e0 + l;
                int k = (int)(val + 0.5f);      // 1 (endpoint) or 2 (self-loop)
                int slot = atomicAdd(&g_ecnt[e], k);
                if (slot < 2) {
                    g_en[e * 2 + slot] = i;
                    if (k == 2) g_en[e * 2 + 1] = i;
                }
            }
        }
    } else if (idx < TN4 + VN4) {
        int t = idx - TN4;
        float4 v = AV[t];
        int base = t * 4;
        int i = base >> 11;         // /Nn
        int j0 = base & (Nn - 1);
        float vals[4] = {v.x, v.y, v.z, v.w};
        #pragma unroll
        for (int l = 0; l < 4; l++) {
            float val = vals[l];
            if (val != 0.f) {
                int j = j0 + l;
                if (i == j) g_vdiag[i] = val;
                else {
                    int slot = atomicAdd(&g_vcnt[i], 1);
                    if (slot < MDV) {
                        g_vcol[i * MDV + slot] = j;
                        g_vvalp[i * MDV + slot] = val;
                    }
                }
            }
        }
    } else {
        int t = idx - TN4 - VN4;
        float4 v = AE[t];
        int base = t * 4;
        int e = base >> 12;         // /Ee
        int f0 = base & (Ee - 1);
        float vals[4] = {v.x, v.y, v.z, v.w};
        #pragma unroll
        for (int l = 0; l < 4; l++) {
            float val = vals[l];
            if (val != 0.f) {
                int f = f0 + l;
                if (e == f) g_ediag[e] = val;
                else {
                    int slot = atomicAdd(&g_ecnt2[e], 1);
                    if (slot < MDE) {
                        g_ecol[e * MDE + slot] = f;
                        g_evalp[e * MDE + slot] = val;
                    }
                }
            }
        }
    }
}

// ---------------- persistent-kernel phase bodies ----------------
__device__ __forceinline__ int find_entry(int row, int col) {
    int cnt = g_vcnt[row]; if (cnt > MDV) cnt = MDV;
    for (int s = 0; s < cnt; s++)
        if (g_vcol[row * MDV + s] == col) return row * MDV + s;
    return -1;
}
__device__ void ph_map() {
    for (int e = blockIdx.x * NT + threadIdx.x; e < Ee; e += GSTRIDE) {
        int a = g_en[2 * e], b = g_en[2 * e + 1];
        if (a > b) { int t = a; a = b; b = t; g_en[2 * e] = a; g_en[2 * e + 1] = b; }
        if (a == b) { g_map0[e] = -1; g_map1[e] = -1; continue; }
        g_map0[e] = find_entry(a, b);
        g_map1[e] = find_entry(b, a);
    }
}

__device__ void ph_dot(const float* __restrict__ A, int lda, int K,
                       const float* __restrict__ p, int R) {
    int w0 = blockIdx.x * (NT / 32) + (threadIdx.x >> 5);
    int lane = threadIdx.x & 31;
    for (int r = w0; r < R; r += NB * (NT / 32)) {
        float acc = 0.f;
        for (int k = lane; k < K; k += 32) acc += A[r * lda + k] * p[k];
        #pragma unroll
        for (int o = 16; o > 0; o >>= 1) acc += __shfl_xor_sync(0xffffffffu, acc, o);
        if (lane == 0) g_s[r] = acc;
    }
}

// 128-col GEMM, 8 subgroups of 128 threads per block
__device__ void ph_gemm128(const float* __restrict__ A, int lda, int K,
                           const float* __restrict__ B, float* __restrict__ out,
                           int ldc, int ocol, int fuse_ln,
                           const float* __restrict__ g, const float* __restrict__ be,
                           float* shAs, float* shRed, int R) {
    int sub = threadIdx.x >> 7;           // 0..7
    int c = threadIdx.x & 127;
    int w = c >> 5, lane = c & 31;
    float* As = shAs + sub * 256;
    const int ngrp = NB * 8;
    int trips = (R + ngrp - 1) / ngrp;
    for (int t = 0; t < trips; t++) {
        int r = t * ngrp + blockIdx.x * 8 + sub;
        bool act = r < R;
        __syncthreads();
        if (act) for (int k = c; k < K; k += 128) As[k] = A[r * lda + k];
        __syncthreads();
        float acc = 0.f;
        if (act) {
            #pragma unroll 8
            for (int k = 0; k < K; k++) acc += As[k] * B[k * 128 + c];
        }
        if (fuse_ln) {
            float v = acc;
            #pragma unroll
            for (int o = 16; o > 0; o >>= 1) v += __shfl_xor_sync(0xffffffffu, v, o);
            if (lane == 0) shRed[sub * 4 + w] = v;
            __syncthreads();
            float mean = (shRed[sub * 4] + shRed[sub * 4 + 1] +
                          shRed[sub * 4 + 2] + shRed[sub * 4 + 3]) * (1.f / 128.f);
            __syncthreads();
            float d = acc - mean;
            v = d * d;
            #pragma unroll
            for (int o = 16; o > 0; o >>= 1) v += __shfl_xor_sync(0xffffffffu, v, o);
            if (lane == 0) shRed[sub * 4 + w] = v;
            __syncthreads();
            float var = (shRed[sub * 4] + shRed[sub * 4 + 1] +
                         shRed[sub * 4 + 2] + shRed[sub * 4 + 3]) * (1.f / 128.f);
            __syncthreads();
            acc = fmaxf(d * rsqrtf(var + 1e-5f) * g[c] + be[c], 0.f);
        }
        if (act) out[r * ldc + ocol + c] = acc;
    }
}

// 16-col GEMM, 64 row-groups of 16 threads per block
__device__ void ph_gemm16(const float* __restrict__ A, int lda, int K,
                          const float* __restrict__ B, float* __restrict__ out,
                          int ldc, int ocol, int reluA, int fuse_ln,
                          const float* __restrict__ g, const float* __restrict__ be,
                          float* shAsf, int R) {
    float (*As)[32] = (float (*)[32])shAsf;
    int rg = threadIdx.x >> 4, c = threadIdx.x & 15;   // rg 0..63
    const int nrows = NB * 64;
    int trips = (R + nrows - 1) / nrows;
    for (int t = 0; t < trips; t++) {
        int r = t * nrows + blockIdx.x * 64 + rg;
        bool act = r < R;
        __syncthreads();
        if (act) for (int k = c; k < K; k += 16) {
            float v = A[r * lda + k];
            if (reluA) v = fmaxf(v, 0.f);
            As[rg][k] = v;
        }
        __syncthreads();
        float acc = 0.f;
        if (act) {
            #pragma unroll 8
            for (int k = 0; k < K; k++) acc += As[rg][k] * B[k * 16 + c];
        }
        if (fuse_ln) {
            float s = acc;
            #pragma unroll
            for (int o = 8; o > 0; o >>= 1) s += __shfl_xor_sync(0xffffffffu, s, o, 16);
            float mean = s * (1.f / 16.f);
            float d = acc - mean;
            float s2 = d * d;
            #pragma unroll
            for (int o = 8; o > 0; o >>= 1) s2 += __shfl_xor_sync(0xffffffffu, s2, o, 16);
            float var = s2 * (1.f / 16.f);
            acc = fmaxf(d * rsqrtf(var + 1e-5f) * g[c] + be[c], 0.f);
        }
        if (act) out[r * ldc + ocol + c] = acc;
    }
}

__device__ void ph_scatter() {
    for (int e = blockIdx.x * NT + threadIdx.x; e < Ee; e += GSTRIDE) {
        int a = g_en[2 * e], b = g_en[2 * e + 1];
        if (a == b) continue;
        float sv = g_s[e];
        int m0 = g_map0[e]; if (m0 >= 0) atomicAdd(&g_msum[m0], sv);
        int m1 = g_map1[e]; if (m1 >= 0) atomicAdd(&g_msum[m1], sv);
    }
}

__device__ void ph_gather_node(const float* __restrict__ bias, float* __restrict__ out,
                               int ldc, int relu) {
    for (int v = blockIdx.x * NT + threadIdx.x; v < Nn * 128; v += GSTRIDE) {
        int i = v >> 7, c = v & 127;
        float acc = bias[c] + g_vdiag[i] * g_HWn[i * 128 + c];
        int cnt = g_vcnt[i]; if (cnt > MDV) cnt = MDV;
        for (int s = 0; s < cnt; s++) {
            int id = i * MDV + s;
            acc += g_msum[id] * g_vvalp[id] * g_HWn[g_vcol[id] * 128 + c];
        }
        if (relu) acc = fmaxf(acc, 0.f);
        out[i * ldc + c] = acc;
    }
}

__device__ void ph_colmax_seed() {
    for (int f = blockIdx.x * NT + threadIdx.x; f < Ee; f += GSTRIDE)
        g_colmax[f] = f2ord(g_ediag[f]);
}
__device__ void ph_msum_clear() {
    for (int i = blockIdx.x * NT + threadIdx.x; i < Nn * MDV; i += GSTRIDE)
        g_msum[i] = 0.f;
}

__device__ void ph_entries() {
    for (int e = blockIdx.x * NT + threadIdx.x; e < Ee; e += GSTRIDE) {
        int a0 = g_en[2 * e], a1 = g_en[2 * e + 1];
        float sa0 = g_s[a0], sa1 = g_s[a1];
        int cnt = g_ecnt2[e]; if (cnt > MDE) cnt = MDE;
        for (int s = 0; s < cnt; s++) {
            int id = e * MDE + s;
            int f = g_ecol[id];
            int b0 = g_en[2 * f], b1 = g_en[2 * f + 1];
            float m = sa0 * ((float)(a0 == b0) + (float)(a0 == b1))
                    + sa1 * ((float)(a1 == b0) + (float)(a1 == b1));
            float av = m * g_evalp[id];
            g_aval[id] = av;
            atomicMax(&g_colmax[f], f2ord(av));
        }
    }
}

__device__ void ph_gather_edge(const float* __restrict__ bias, float* __restrict__ out,
                               int ldc, int relu) {
    for (int v = blockIdx.x * NT + threadIdx.x; v < Ee * 16; v += GSTRIDE) {
        int e = v >> 4, c = v & 15;
        float acc = bias[c] + g_ediag[e] * (1.f / ord2f(g_colmax[e])) * g_HWe[e * 16 + c];
        int cnt = g_ecnt2[e]; if (cnt > MDE) cnt = MDE;
        for (int s = 0; s < cnt; s++) {
            int id = e * MDE + s;
            int f = g_ecol[id];
            acc += g_aval[id] * (1.f / ord2f(g_colmax[f])) * g_HWe[f * 16 + c];
        }
        if (relu) acc = fmaxf(acc, 0.f);
        out[e * ldc + c] = acc;
    }
}

// ---------------- persistent kernel: everything after the scan ----------------
__global__ void __launch_bounds__(NT) k_all(
    const float* __restrict__ X, const float* __restrict__ Z,
    const float* __restrict__ W1, const float* __restrict__ p1, const float* __restrict__ b1,
    const float* __restrict__ Wf1, const float* __restrict__ g1, const float* __restrict__ be1,
    const float* __restrict__ W2, const float* __restrict__ p2, const float* __restrict__ b2,
    const float* __restrict__ Wf2, const float* __restrict__ g2, const float* __restrict__ be2,
    const float* __restrict__ W3, const float* __restrict__ p3, const float* __restrict__ b3,
    const float* __restrict__ W4, const float* __restrict__ p4, const float* __restrict__ b4,
    const float* __restrict__ W5, const float* __restrict__ p5, const float* __restrict__ b5,
    float* __restrict__ out)
{
    __shared__ float shAs[2048];
    __shared__ float shRed[32];

    // P2: map + s1 + HW1 + F1(LN) + F2(LN)   (all independent)
    ph_map();
    ph_dot(Z, 16, 16, p1, Ee);                                        // s1
    ph_gemm128(X, 64, 64, W1, g_HWn, 128, 0, 0, 0, 0, shAs, shRed, Nn);     // HW1
    ph_gemm128(X, 64, 64, Wf1, g_X1F1, 256, 128, 1, g1, be1, shAs, shRed, Nn); // F1
    ph_gemm16(Z, 16, 16, Wf2, g_Z2F2, 32, 16, 0, 1, g2, be2, shAs, Ee);     // F2
    gbar();
    // P3: scatter s1 into msum (msum zeroed by k_clear)
    ph_scatter();
    gbar();
    // P4: gather -> X1 (relu) into X1F1[:, :128]
    ph_gather_node(b1, g_X1F1, 256, 1);
    gbar();
    // P5: s2 + HW2 + colmax seed + msum clear + HW3
    ph_dot(g_X1F1, 256, 256, p2, Nn);                                 // s2
    ph_gemm16(Z, 16, 16, W2, g_HWe, 16, 0, 1, 0, 0, 0, shAs, Ee);     // relu(Z)@W2
    ph_colmax_seed();
    ph_msum_clear();
    ph_gemm128(g_X1F1, 256, 256, W3, g_HWn, 128, 0, 0, 0, 0, shAs, shRed, Nn); // HW3
    gbar();
    // P6: edge entries (aval + colmax)
    ph_entries();
    gbar();
    // P7: gather edge -> Z2 (relu) into Z2F2[:, :16]
    ph_gather_edge(b2, g_Z2F2, 32, 1);
    gbar();
    // P8: s3 + HW4 + colmax re-seed (for gc4)
    ph_dot(g_Z2F2, 32, 32, p3, Ee);                                   // s3
    ph_gemm16(g_Z2F2, 32, 32, W4, g_HWe, 16, 0, 0, 0, 0, 0, shAs, Ee);// HW4
    ph_colmax_seed();
    gbar();
    // P9: scatter s3
    ph_scatter();
    gbar();
    // P10: gather -> X3 (relu)
    ph_gather_node(b3, g_X3, 128, 1);
    gbar();
    // P11: s4 + msum clear (for gc5)
    ph_dot(g_X3, 128, 128, p4, Nn);                                   // s4
    ph_msum_clear();
    gbar();
    // P12: edge entries
    ph_entries();
    gbar();
    // P13: gather edge -> Z4 (relu)
    ph_gather_edge(b4, g_Z4, 16, 1);
    gbar();
    // P14: s5 + HW5
    ph_dot(g_Z4, 16, 16, p5, Ee);                                     // s5
    ph_gemm128(g_X3, 128, 128, W5, g_HWn, 128, 0, 0, 0, 0, shAs, shRed, Nn); // HW5
    gbar();
    // P15: scatter s5
    ph_scatter();
    gbar();
    // P16: gather -> out (no relu)
    ph_gather_node(b5, out, 128, 0);
}

// ---------------- host launcher ----------------
extern "C" void kernel_launch(void* const* d_in, const int* in_sizes, int n_in,
                              void* d_out, int out_size) {
    (void)in_sizes; (void)n_in; (void)out_size;
    const float* X     = (const float*)d_in[0];
    const float* Z     = (const float*)d_in[1];
    const float* adj_e = (const float*)d_in[2];
    const float* adj_v = (const float*)d_in[3];
    const float* T     = (const float*)d_in[4];

    k_clear<<<(Nn * MDV + 255) / 256, 256>>>();
    k_scan<<<(TN4 + VN4 + EN4) / 256, 256>>>((const float4*)T, (const float4*)adj_v,
                                             (const float4*)adj_e);
    k_all<<<NB, NT>>>(
        X, Z,
        (const float*)d_in[5], (const float*)d_in[6], (const float*)d_in[7],
        (const float*)d_in[8], (const float*)d_in[9], (const float*)d_in[10],
        (const float*)d_in[11], (const float*)d_in[12], (const float*)d_in[13],
        (const float*)d_in[14], (const float*)d_in[15], (const float*)d_in[16],
        (const float*)d_in[17], (const float*)d_in[18], (const float*)d_in[19],
        (const float*)d_in[20], (const float*)d_in[21], (const float*)d_in[22],
        (const float*)d_in[23], (const float*)d_in[24], (const float*)d_in[25],
        (float*)d_out);
}

// round 9
// speedup vs baseline: 1.2951x; 1.0456x over previous
#include <cuda_runtime.h>

#define Nn 2048
#define Ee 4096
#define MDV 32
#define MDE 32
#define LMAX 4
#define NB 148
#define NT 1024
#define GSTRIDE (NB * NT)

#define TN4 (Nn * Ee / 4)
#define VN4 (Nn * Nn / 4)
#define EN4 (Ee * Ee / 4)

// ---------------- static device state ----------------
static __device__ int      g_en[Ee * 2];        // edge endpoints (a,b) sorted
static __device__ int      g_ecnt[Ee];          // T-scan slot counter
static __device__ int      g_vcnt[Nn];          // adj_v padded-row counts
static __device__ float    g_vdiag[Nn];
static __device__ int      g_vcol[Nn * MDV];
static __device__ float    g_vvalp[Nn * MDV];
static __device__ int      g_lcnt[Nn * MDV];    // per-entry contributing-edge count
static __device__ int      g_elist[Nn * MDV * LMAX];
static __device__ int      g_ecnt2[Ee];         // adj_e padded-row counts
static __device__ float    g_ediag[Ee];
static __device__ int      g_ecol[Ee * MDE];
static __device__ float    g_evalp[Ee * MDE];
static __device__ float    g_aval[Ee * MDE];
static __device__ unsigned g_colmaxA[Ee];       // gc2 column max
static __device__ unsigned g_colmaxB[Ee];       // gc4 column max
static __device__ float    g_X1F1[Nn * 256];
static __device__ float    g_HWn[Nn * 128];     // HW1/HW3/HW5
static __device__ float    g_X3[Nn * 128];
static __device__ float    g_Z2F2[Ee * 32];
static __device__ float    g_HWe[Ee * 16];      // HW2/HW4
static __device__ float    g_Z4[Ee * 16];
static __device__ float    g_s1[Ee];
static __device__ float    g_s2[Nn];
static __device__ float    g_s3[Ee];
static __device__ float    g_s4[Nn];
static __device__ float    g_s5[Ee];
static __device__ unsigned g_barArr;
static __device__ unsigned g_barGen;

// ---------------- helpers ----------------
__device__ __forceinline__ unsigned f2ord(float f) {
    unsigned u = __float_as_uint(f);
    return (u & 0x80000000u) ? ~u : (u | 0x80000000u);
}
__device__ __forceinline__ float ord2f(unsigned u) {
    return __uint_as_float((u & 0x80000000u) ? (u & 0x7fffffffu) : ~u);
}

__device__ __forceinline__ void gbar() {
    __syncthreads();
    if (threadIdx.x == 0) {
        unsigned gen = *((volatile unsigned*)&g_barGen);
        __threadfence();
        unsigned t = atomicAdd(&g_barArr, 1u);
        if (t == NB - 1) {
            atomicExch(&g_barArr, 0u);
            __threadfence();
            atomicAdd(&g_barGen, 1u);
        } else {
            while (*((volatile unsigned*)&g_barGen) == gen) __nanosleep(32);
        }
    }
    __syncthreads();
}

// ---------------- standalone kernels ----------------
// clears ONLY what k_scan's atomics need (small, fast)
__global__ void k_clear() {
    int i = blockIdx.x * 256 + threadIdx.x;
    if (i < Ee) { g_ecnt[i] = 0; g_ecnt2[i] = 0; }
    if (i < Nn) g_vcnt[i] = 0;
}

// fused single-pass scan of T, adj_v, adj_e + clearing of k_all-only state
// (g_lcnt / g_s2..s5 are untouched by the scan atomics -> no ordering hazard)
__global__ void k_scan(const float4* __restrict__ T, const float4* __restrict__ AV,
                       const float4* __restrict__ AE) {
    int idx = blockIdx.x * 256 + threadIdx.x;
    // piggyback clears on the first blocks' threads (disjoint from scan outputs)
    if (idx < Nn * MDV) g_lcnt[idx] = 0;
    if (idx < Ee) { g_s3[idx] = 0.f; g_s5[idx] = 0.f; }
    if (idx < Nn) { g_s2[idx] = 0.f; g_s4[idx] = 0.f; }

    if (idx < TN4) {
        float4 v = __ldcs(&T[idx]);
        int base = idx * 4;
        int i = base >> 12;
        int e0 = base & (Ee - 1);
        float vals[4] = {v.x, v.y, v.z, v.w};
        #pragma unroll
        for (int l = 0; l < 4; l++) {
            float val = vals[l];
            if (val != 0.f) {
                int e = e0 + l;
                int k = (int)(val + 0.5f);      // 1 (endpoint) or 2 (self-loop)
                int slot = atomicAdd(&g_ecnt[e], k);
                if (slot < 2) {
                    g_en[e * 2 + slot] = i;
                    if (k == 2) g_en[e * 2 + 1] = i;
                }
            }
        }
    } else if (idx < TN4 + VN4) {
        int t = idx - TN4;
        float4 v = __ldcs(&AV[t]);
        int base = t * 4;
        int i = base >> 11;
        int j0 = base & (Nn - 1);
        float vals[4] = {v.x, v.y, v.z, v.w};
        #pragma unroll
        for (int l = 0; l < 4; l++) {
            float val = vals[l];
            if (val != 0.f) {
                int j = j0 + l;
                if (i == j) g_vdiag[i] = val;
                else {
                    int slot = atomicAdd(&g_vcnt[i], 1);
                    if (slot < MDV) {
                        g_vcol[i * MDV + slot] = j;
                        g_vvalp[i * MDV + slot] = val;
                    }
                }
            }
        }
    } else {
        int t = idx - TN4 - VN4;
        float4 v = __ldcs(&AE[t]);
        int base = t * 4;
        int e = base >> 12;
        int f0 = base & (Ee - 1);
        float vals[4] = {v.x, v.y, v.z, v.w};
        #pragma unroll
        for (int l = 0; l < 4; l++) {
            float val = vals[l];
            if (val != 0.f) {
                int f = f0 + l;
                if (e == f) g_ediag[e] = val;
                else {
                    int slot = atomicAdd(&g_ecnt2[e], 1);
                    if (slot < MDE) {
                        g_ecol[e * MDE + slot] = f;
                        g_evalp[e * MDE + slot] = val;
                    }
                }
            }
        }
    }
}

// ---------------- persistent phase bodies ----------------
__device__ __forceinline__ int find_entry(int row, int col) {
    int cnt = g_vcnt[row]; if (cnt > MDV) cnt = MDV;
    for (int s = 0; s < cnt; s++)
        if (g_vcol[row * MDV + s] == col) return row * MDV + s;
    return -1;
}

// build per-entry contributing-edge lists (replaces scatter phases)
__device__ void ph_map() {
    for (int e = blockIdx.x * NT + threadIdx.x; e < Ee; e += GSTRIDE) {
        int a = g_en[2 * e], b = g_en[2 * e + 1];
        if (a > b) { int t = a; a = b; b = t; g_en[2 * e] = a; g_en[2 * e + 1] = b; }
        if (a == b) continue;
        int id0 = find_entry(a, b);
        if (id0 >= 0) {
            int slot = atomicAdd(&g_lcnt[id0], 1);
            if (slot < LMAX) g_elist[id0 * LMAX + slot] = e;
        }
        int id1 = find_entry(b, a);
        if (id1 >= 0) {
            int slot = atomicAdd(&g_lcnt[id1], 1);
            if (slot < LMAX) g_elist[id1 * LMAX + slot] = e;
        }
    }
}

__device__ void ph_dot(const float* __restrict__ A, int lda, int K,
                       const float* __restrict__ p, float* __restrict__ sdst, int R) {
    int w0 = blockIdx.x * (NT / 32) + (threadIdx.x >> 5);
    int lane = threadIdx.x & 31;
    for (int r = w0; r < R; r += NB * (NT / 32)) {
        float acc = 0.f;
        for (int k = lane; k < K; k += 32) acc += A[r * lda + k] * p[k];
        #pragma unroll
        for (int o = 16; o > 0; o >>= 1) acc += __shfl_xor_sync(0xffffffffu, acc, o);
        if (lane == 0) sdst[r] = acc;
    }
}

__device__ void ph_colmax_seed() {
    for (int f = blockIdx.x * NT + threadIdx.x; f < Ee; f += GSTRIDE) {
        unsigned v = f2ord(g_ediag[f]);
        g_colmaxA[f] = v;
        g_colmaxB[f] = v;
    }
}

// 128-col GEMM, 8 subgroups of 128 threads; optional LN+relu; optional s-seed
__device__ void ph_gemm128(const float* __restrict__ A, int lda, int K,
                           const float* __restrict__ B, float* __restrict__ out,
                           int ldc, int ocol, int fuse_ln,
                           const float* __restrict__ g, const float* __restrict__ be,
                           float* shAs, float* shRed, int R,
                           float* __restrict__ sacc, const float* __restrict__ pvec) {
    int sub = threadIdx.x >> 7;
    int c = threadIdx.x & 127;
    int w = c >> 5, lane = c & 31;
    float* As = shAs + sub * 256;
    const int ngrp = NB * 8;
    int trips = (R + ngrp - 1) / ngrp;
    for (int t = 0; t < trips; t++) {
        int r = t * ngrp + blockIdx.x * 8 + sub;
        bool act = r < R;
        __syncthreads();
        if (act) for (int k = c; k < K; k += 128) As[k] = A[r * lda + k];
        __syncthreads();
        float acc = 0.f;
        if (act) {
            #pragma unroll 8
            for (int k = 0; k < K; k++) acc += As[k] * B[k * 128 + c];
        }
        if (fuse_ln) {
            float v = acc;
            #pragma unroll
            for (int o = 16; o > 0; o >>= 1) v += __shfl_xor_sync(0xffffffffu, v, o);
            if (lane == 0) shRed[sub * 4 + w] = v;
            __syncthreads();
            float mean = (shRed[sub * 4] + shRed[sub * 4 + 1] +
                          shRed[sub * 4 + 2] + shRed[sub * 4 + 3]) * (1.f / 128.f);
            __syncthreads();
            float d = acc - mean;
            v = d * d;
            #pragma unroll
            for (int o = 16; o > 0; o >>= 1) v += __shfl_xor_sync(0xffffffffu, v, o);
            if (lane == 0) shRed[sub * 4 + w] = v;
            __syncthreads();
            float var = (shRed[sub * 4] + shRed[sub * 4 + 1] +
                         shRed[sub * 4 + 2] + shRed[sub * 4 + 3]) * (1.f / 128.f);
            __syncthreads();
            acc = fmaxf(d * rsqrtf(var + 1e-5f) * g[c] + be[c], 0.f);
        }
        if (act) {
            out[r * ldc + ocol + c] = acc;
            if (sacc) {
                float con = acc * pvec[ocol + c];
                #pragma unroll
                for (int o = 16; o > 0; o >>= 1) con += __shfl_xor_sync(0xffffffffu, con, o);
                if (lane == 0) atomicAdd(&sacc[r], con);
            }
        }
    }
}

// 16-col GEMM, 64 row-groups of 16 threads; optional relu on A, LN+relu, s-seed
__device__ void ph_gemm16(const float* __restrict__ A, int lda, int K,
                          const float* __restrict__ B, float* __restrict__ out,
                          int ldc, int ocol, int reluA, int fuse_ln,
                          const float* __restrict__ g, const float* __restrict__ be,
                          float* shAsf, int R,
                          float* __restrict__ sacc, const float* __restrict__ pvec) {
    float (*As)[32] = (float (*)[32])shAsf;
    int rg = threadIdx.x >> 4, c = threadIdx.x & 15;
    int lane = threadIdx.x & 31;
    const int nrows = NB * 64;
    int trips = (R + nrows - 1) / nrows;
    for (int t = 0; t < trips; t++) {
        int r = t * nrows + blockIdx.x * 64 + rg;
        bool act = r < R;
        __syncthreads();
        if (act) for (int k = c; k < K; k += 16) {
            float v = A[r * lda + k];
            if (reluA) v = fmaxf(v, 0.f);
            As[rg][k] = v;
        }
        __syncthreads();
        float acc = 0.f;
        if (act) {
            #pragma unroll 8
            for (int k = 0; k < K; k++) acc += As[rg][k] * B[k * 16 + c];
        }
        if (fuse_ln) {
            float s = acc;
            #pragma unroll
            for (int o = 8; o > 0; o >>= 1) s += __shfl_xor_sync(0xffffffffu, s, o, 16);
            float mean = s * (1.f / 16.f);
            float d = acc - mean;
            float s2 = d * d;
            #pragma unroll
            for (int o = 8; o > 0; o >>= 1) s2 += __shfl_xor_sync(0xffffffffu, s2, o, 16);
            float var = s2 * (1.f / 16.f);
            acc = fmaxf(d * rsqrtf(var + 1e-5f) * g[c] + be[c], 0.f);
        }
        if (act) {
            out[r * ldc + ocol + c] = acc;
            if (sacc) {
                float con = acc * pvec[ocol + c];
                #pragma unroll
                for (int o = 8; o > 0; o >>= 1) con += __shfl_xor_sync(0xffffffffu, con, o, 16);
                if ((lane & 15) == 0) atomicAdd(&sacc[r], con);
            }
        }
    }
}

// node gather with inline msum from edge lists; optional s-accumulation
__device__ void ph_gather_node(const float* __restrict__ sgate,
                               const float* __restrict__ bias, float* __restrict__ out,
                               int ldc, int relu,
                               float* __restrict__ sacc, const float* __restrict__ pvec) {
    int lane = threadIdx.x & 31;
    for (int v = blockIdx.x * NT + threadIdx.x; v < Nn * 128; v += GSTRIDE) {
        int i = v >> 7, c = v & 127;
        float acc = bias[c] + g_vdiag[i] * g_HWn[i * 128 + c];
        int cnt = g_vcnt[i]; if (cnt > MDV) cnt = MDV;
        for (int s = 0; s < cnt; s++) {
            int id = i * MDV + s;
            int lc = g_lcnt[id]; if (lc > LMAX) lc = LMAX;
            float ms = 0.f;
            for (int l = 0; l < lc; l++) ms += sgate[g_elist[id * LMAX + l]];
            acc += ms * g_vvalp[id] * g_HWn[g_vcol[id] * 128 + c];
        }
        if (relu) acc = fmaxf(acc, 0.f);
        out[i * ldc + c] = acc;
        if (sacc) {
            float con = acc * pvec[c];
            #pragma unroll
            for (int o = 16; o > 0; o >>= 1) con += __shfl_xor_sync(0xffffffffu, con, o);
            if (lane == 0) atomicAdd(&sacc[i], con);
        }
    }
}

__device__ void ph_entries(const float* __restrict__ sgate, unsigned* __restrict__ colmax) {
    for (int e = blockIdx.x * NT + threadIdx.x; e < Ee; e += GSTRIDE) {
        int a0 = g_en[2 * e], a1 = g_en[2 * e + 1];
        float sa0 = sgate[a0], sa1 = sgate[a1];
        int cnt = g_ecnt2[e]; if (cnt > MDE) cnt = MDE;
        for (int s = 0; s < cnt; s++) {
            int id = e * MDE + s;
            int f = g_ecol[id];
            int b0 = g_en[2 * f], b1 = g_en[2 * f + 1];
            float m = sa0 * ((float)(a0 == b0) + (float)(a0 == b1))
                    + sa1 * ((float)(a1 == b0) + (float)(a1 == b1));
            float av = m * g_evalp[id];
            g_aval[id] = av;
            atomicMax(&colmax[f], f2ord(av));
        }
    }
}

__device__ void ph_gather_edge(const unsigned* __restrict__ colmax,
                               const float* __restrict__ bias, float* __restrict__ out,
                               int ldc, int relu,
                               float* __restrict__ sacc, const float* __restrict__ pvec) {
    int lane = threadIdx.x & 31;
    for (int v = blockIdx.x * NT + threadIdx.x; v < Ee * 16; v += GSTRIDE) {
        int e = v >> 4, c = v & 15;
        float acc = bias[c] + g_ediag[e] * (1.f / ord2f(colmax[e])) * g_HWe[e * 16 + c];
        int cnt = g_ecnt2[e]; if (cnt > MDE) cnt = MDE;
        for (int s = 0; s < cnt; s++) {
            int id = e * MDE + s;
            int f = g_ecol[id];
            acc += g_aval[id] * (1.f / ord2f(colmax[f])) * g_HWe[f * 16 + c];
        }
        if (relu) acc = fmaxf(acc, 0.f);
        out[e * ldc + c] = acc;
        if (sacc) {
            float con = acc * pvec[c];
            #pragma unroll
            for (int o = 8; o > 0; o >>= 1) con += __shfl_xor_sync(0xffffffffu, con, o, 16);
            if ((lane & 15) == 0) atomicAdd(&sacc[e], con);
        }
    }
}

// ---------------- persistent kernel: 8 phases, 7 grid barriers ----------------
__global__ void __launch_bounds__(NT) k_all(
    const float* __restrict__ X, const float* __restrict__ Z,
    const float* __restrict__ W1, const float* __restrict__ p1, const float* __restrict__ b1,
    const float* __restrict__ Wf1, const float* __restrict__ g1, const float* __restrict__ be1,
    const float* __restrict__ W2, const float* __restrict__ p2, const float* __restrict__ b2,
    const float* __restrict__ Wf2, const float* __restrict__ g2, const float* __restrict__ be2,
    const float* __restrict__ W3, const float* __restrict__ p3, const float* __restrict__ b3,
    const float* __restrict__ W4, const float* __restrict__ p4, const float* __restrict__ b4,
    const float* __restrict__ W5, const float* __restrict__ p5, const float* __restrict__ b5,
    float* __restrict__ out)
{
    __shared__ float shAs[2048];
    __shared__ float shRed[32];

    // P2: map + s1 + HW1 + F1(LN, seed s2) + F2(LN, seed s3) + HW2 + colmax seeds
    ph_map();
    ph_dot(Z, 16, 16, p1, g_s1, Ee);                                      // s1
    ph_colmax_seed();
    ph_gemm128(X, 64, 64, W1, g_HWn, 128, 0, 0, 0, 0, shAs, shRed, Nn, 0, 0);        // HW1
    ph_gemm128(X, 64, 64, Wf1, g_X1F1, 256, 128, 1, g1, be1, shAs, shRed, Nn, g_s2, p2); // F1 + s2 seed
    ph_gemm16(Z, 16, 16, Wf2, g_Z2F2, 32, 16, 0, 1, g2, be2, shAs, Ee, g_s3, p3);    // F2 + s3 seed
    ph_gemm16(Z, 16, 16, W2, g_HWe, 16, 0, 1, 0, 0, 0, shAs, Ee, 0, 0);              // HW2
    gbar();
    // P3: gather X1 (inline msum from s1) + accumulate s2
    ph_gather_node(g_s1, b1, g_X1F1, 256, 1, g_s2, p2);
    gbar();
    // P4: gc2 entries (s2, colmaxA) + HW3 (needs X1F1)
    ph_entries(g_s2, g_colmaxA);
    ph_gemm128(g_X1F1, 256, 256, W3, g_HWn, 128, 0, 0, 0, 0, shAs, shRed, Nn, 0, 0); // HW3
    gbar();
    // P5: gather Z2 + accumulate s3
    ph_gather_edge(g_colmaxA, b2, g_Z2F2, 32, 1, g_s3, p3);
    gbar();
    // P6: gather X3 (s3 lists, HW3) + accumulate s4 + HW4 (needs Z2F2)
    ph_gather_node(g_s3, b3, g_X3, 128, 1, g_s4, p4);
    ph_gemm16(g_Z2F2, 32, 32, W4, g_HWe, 16, 0, 0, 0, 0, 0, shAs, Ee, 0, 0);         // HW4
    gbar();
    // P7: gc4 entries (s4, colmaxB) + HW5 (needs X3)
    ph_entries(g_s4, g_colmaxB);
    ph_gemm128(g_X3, 128, 128, W5, g_HWn, 128, 0, 0, 0, 0, shAs, shRed, Nn, 0, 0);   // HW5
    gbar();
    // P8: gather Z4 + accumulate s5
    ph_gather_edge(g_colmaxB, b4, g_Z4, 16, 1, g_s5, p5);
    gbar();
    // P9: gather out (s5 lists, HW5), no relu
    ph_gather_node(g_s5, b5, out, 128, 0, 0, 0);
}

// ---------------- host launcher ----------------
extern "C" void kernel_launch(void* const* d_in, const int* in_sizes, int n_in,
                              void* d_out, int out_size) {
    (void)in_sizes; (void)n_in; (void)out_size;
    const float* X     = (const float*)d_in[0];
    const float* Z     = (const float*)d_in[1];
    const float* adj_e = (const float*)d_in[2];
    const float* adj_v = (const float*)d_in[3];
    const float* T     = (const float*)d_in[4];

    k_clear<<<(Ee + 255) / 256, 256>>>();
    k_scan<<<(TN4 + VN4 + EN4) / 256, 256>>>((const float4*)T, (const float4*)adj_v,
                                             (const float4*)adj_e);
    k_all<<<NB, NT>>>(
        X, Z,
        (const float*)d_in[5], (const float*)d_in[6], (const float*)d_in[7],
        (const float*)d_in[8], (const float*)d_in[9], (const float*)d_in[10],
        (const float*)d_in[11], (const float*)d_in[12], (const float*)d_in[13],
        (const float*)d_in[14], (const float*)d_in[15], (const float*)d_in[16],
        (const float*)d_in[17], (const float*)d_in[18], (const float*)d_in[19],
        (const float*)d_in[20], (const float*)d_in[21], (const float*)d_in[22],
        (const float*)d_in[23], (const float*)d_in[24], (const float*)d_in[25],
        (float*)d_out);
}

// round 13
// speedup vs baseline: 1.4568x; 1.1248x over previous
#include <cuda_runtime.h>

#define Nn 2048
#define Ee 4096
#define MDV 32
#define MDE 32
#define LMAX 4
#define NB 148
#define NT 1024
#define GSTRIDE (NB * NT)

#define TN4 (Nn * Ee / 4)
#define VN4 (Nn * Nn / 4)
#define EN4 (Ee * Ee / 4)
#define TOT4 (TN4 + VN4 + EN4)        // 7340032
#define NSCAN (TOT4 / 2048)           // 3584 blocks, 8 float4 loads per thread
#define NFRONT 2624
#define NGRID (NFRONT + NSCAN)

// ---------------- static device state ----------------
static __device__ int      g_en[Ee * 2];        // edge endpoints (a,b) sorted
static __device__ int      g_ecnt[Ee];
static __device__ int      g_vcnt[Nn];
static __device__ float    g_vdiag[Nn];
static __device__ int      g_vcol[Nn * MDV];
static __device__ float    g_vvalp[Nn * MDV];
static __device__ int      g_lcnt[Nn * MDV];
static __device__ int      g_elist[Nn * MDV * LMAX];
static __device__ int      g_ecnt2[Ee];
static __device__ float    g_ediag[Ee];
static __device__ int      g_ecol[Ee * MDE];
static __device__ float    g_evalp[Ee * MDE];
static __device__ float    g_aval[Ee * MDE];
static __device__ unsigned g_colmaxA[Ee];
static __device__ unsigned g_colmaxB[Ee];
static __device__ float    g_X1F1[Nn * 256];
static __device__ float    g_HWn[Nn * 128];
static __device__ float    g_X3[Nn * 128];
static __device__ float    g_Z2F2[Ee * 32];
static __device__ float    g_HWe[Ee * 16];
static __device__ float    g_Z4[Ee * 16];
static __device__ float    g_s1[Ee];
static __device__ float    g_s2[Nn];
static __device__ float    g_s3[Ee];
static __device__ float    g_s4[Nn];
static __device__ float    g_s5[Ee];
static __device__ unsigned g_barArr;
static __device__ unsigned g_barGen;

// ---------------- helpers ----------------
__device__ __forceinline__ unsigned f2ord(float f) {
    unsigned u = __float_as_uint(f);
    return (u & 0x80000000u) ? ~u : (u | 0x80000000u);
}
__device__ __forceinline__ float ord2f(unsigned u) {
    return __uint_as_float((u & 0x80000000u) ? (u & 0x7fffffffu) : ~u);
}

__device__ __forceinline__ void gbar() {
    __syncthreads();
    if (threadIdx.x == 0) {
        unsigned gen = *((volatile unsigned*)&g_barGen);
        __threadfence();
        unsigned t = atomicAdd(&g_barArr, 1u);
        if (t == NB - 1) {
            atomicExch(&g_barArr, 0u);
            __threadfence();
            atomicAdd(&g_barGen, 1u);
        } else {
            while (*((volatile unsigned*)&g_barGen) == gen) __nanosleep(32);
        }
    }
    __syncthreads();
}

// ---------------- k_clear: scan counters + s accumulators ----------------
__global__ void k_clear() {
    int i = blockIdx.x * 256 + threadIdx.x;
    if (i < Ee) { g_ecnt[i] = 0; g_ecnt2[i] = 0; g_s3[i] = 0.f; g_s5[i] = 0.f; }
    if (i < Nn) { g_vcnt[i] = 0; g_s2[i] = 0.f; g_s4[i] = 0.f; }
}

// ---------------- scan element processing ----------------
__device__ __forceinline__ void scan_elem(int idx, float4 v) {
    int base = idx * 4;
    float vals[4] = {v.x, v.y, v.z, v.w};
    if (idx < TN4) {
        int i = base >> 12;
        int e0 = base & (Ee - 1);
        #pragma unroll
        for (int l = 0; l < 4; l++) {
            float val = vals[l];
            if (val != 0.f) {
                int e = e0 + l;
                int k = (int)(val + 0.5f);
                int slot = atomicAdd(&g_ecnt[e], k);
                if (slot < 2) {
                    g_en[e * 2 + slot] = i;
                    if (k == 2) g_en[e * 2 + 1] = i;
                }
            }
        }
    } else if (idx < TN4 + VN4) {
        int t = idx - TN4;
        int b2 = t * 4;
        int i = b2 >> 11;
        int j0 = b2 & (Nn - 1);
        #pragma unroll
        for (int l = 0; l < 4; l++) {
            float val = vals[l];
            if (val != 0.f) {
                int j = j0 + l;
                if (i == j) g_vdiag[i] = val;
                else {
                    int slot = atomicAdd(&g_vcnt[i], 1);
                    if (slot < MDV) {
                        g_vcol[i * MDV + slot] = j;
                        g_vvalp[i * MDV + slot] = val;
                    }
                }
            }
        }
    } else {
        int t = idx - TN4 - VN4;
        int b2 = t * 4;
        int e = b2 >> 12;
        int f0 = b2 & (Ee - 1);
        #pragma unroll
        for (int l = 0; l < 4; l++) {
            float val = vals[l];
            if (val != 0.f) {
                int f = f0 + l;
                if (e == f) g_ediag[e] = val;
                else {
                    int slot = atomicAdd(&g_ecnt2[e], 1);
                    if (slot < MDE) {
                        g_ecol[e * MDE + slot] = f;
                        g_evalp[e * MDE + slot] = val;
                    }
                }
            }
        }
    }
}

__device__ __forceinline__ const float4* scan_addr(
        int idx, const float4* T, const float4* AV, const float4* AE) {
    if (idx < TN4) return T + idx;
    if (idx < TN4 + VN4) return AV + (idx - TN4);
    return AE + (idx - TN4 - VN4);
}

// ---------------- front jobs (256-thread blocks, input-only deps) ----------------
// 2 rows/block, K=64, C=128; optional LN+relu and s-seed
__device__ void front_gemm128(int rbase, const float* __restrict__ A,
                              const float* __restrict__ B, float* __restrict__ out,
                              int ldc, int ocol, int ln,
                              const float* __restrict__ g, const float* __restrict__ be,
                              float* __restrict__ sacc, const float* __restrict__ pvec) {
    __shared__ float As[2][64];
    __shared__ float red[2][4];
    int sub = threadIdx.x >> 7;
    int c = threadIdx.x & 127;
    int w = c >> 5, lane = c & 31;
    int r = rbase + sub;
    if (c < 64) As[sub][c] = A[r * 64 + c];
    __syncthreads();
    float acc = 0.f;
    #pragma unroll 8
    for (int k = 0; k < 64; k++) acc += As[sub][k] * B[k * 128 + c];
    if (ln) {
        float v = acc;
        #pragma unroll
        for (int o = 16; o > 0; o >>= 1) v += __shfl_xor_sync(0xffffffffu, v, o);
        if (lane == 0) red[sub][w] = v;
        __syncthreads();
        float mean = (red[sub][0] + red[sub][1] + red[sub][2] + red[sub][3]) * (1.f / 128.f);
        __syncthreads();
        float d = acc - mean;
        v = d * d;
        #pragma unroll
        for (int o = 16; o > 0; o >>= 1) v += __shfl_xor_sync(0xffffffffu, v, o);
        if (lane == 0) red[sub][w] = v;
        __syncthreads();
        float var = (red[sub][0] + red[sub][1] + red[sub][2] + red[sub][3]) * (1.f / 128.f);
        acc = fmaxf(d * rsqrtf(var + 1e-5f) * g[c] + be[c], 0.f);
    }
    out[r * ldc + ocol + c] = acc;
    if (sacc) {
        float con = acc * pvec[ocol + c];
        #pragma unroll
        for (int o = 16; o > 0; o >>= 1) con += __shfl_xor_sync(0xffffffffu, con, o);
        if (lane == 0) atomicAdd(&sacc[r], con);
    }
}

// 16 rows/block, K=16, C=16; optional relu on A, LN+relu, s-seed
__device__ void front_gemm16(int rbase, const float* __restrict__ A,
                             const float* __restrict__ B, float* __restrict__ out,
                             int ldc, int ocol, int reluA, int ln,
                             const float* __restrict__ g, const float* __restrict__ be,
                             float* __restrict__ sacc, const float* __restrict__ pvec) {
    __shared__ float As[16][17];
    int rg = threadIdx.x >> 4, c = threadIdx.x & 15;
    int lane = threadIdx.x & 31;
    int r = rbase + rg;
    float v0 = A[r * 16 + c];
    if (reluA) v0 = fmaxf(v0, 0.f);
    As[rg][c] = v0;
    __syncthreads();
    float acc = 0.f;
    #pragma unroll
    for (int k = 0; k < 16; k++) acc += As[rg][k] * B[k * 16 + c];
    if (ln) {
        float s = acc;
        #pragma unroll
        for (int o = 8; o > 0; o >>= 1) s += __shfl_xor_sync(0xffffffffu, s, o, 16);
        float mean = s * (1.f / 16.f);
        float d = acc - mean;
        float s2 = d * d;
        #pragma unroll
        for (int o = 8; o > 0; o >>= 1) s2 += __shfl_xor_sync(0xffffffffu, s2, o, 16);
        float var = s2 * (1.f / 16.f);
        acc = fmaxf(d * rsqrtf(var + 1e-5f) * g[c] + be[c], 0.f);
    }
    out[r * ldc + ocol + c] = acc;
    if (sacc) {
        float con = acc * pvec[ocol + c];
        #pragma unroll
        for (int o = 8; o > 0; o >>= 1) con += __shfl_xor_sync(0xffffffffu, con, o, 16);
        if ((lane & 15) == 0) atomicAdd(&sacc[r], con);
    }
}

// s1 = Z·p1 (K=16); 64 blocks × 8 warps, each warp 8 rows strided
__device__ void front_dot(int blk, const float* __restrict__ Z,
                          const float* __restrict__ p1) {
    int wid = threadIdx.x >> 5, lane = threadIdx.x & 31;
    int w0 = blk * 8 + wid;      // 0..511
    for (int r = w0; r < Ee; r += 512) {
        float acc = (lane < 16) ? Z[r * 16 + lane] * p1[lane] : 0.f;
        #pragma unroll
        for (int o = 16; o > 0; o >>= 1) acc += __shfl_xor_sync(0xffffffffu, acc, o);
        if (lane == 0) g_s1[r] = acc;
    }
}

// ---------------- fused scan + front kernel ----------------
__global__ void __launch_bounds__(256) k_scanfront(
    const float4* __restrict__ T, const float4* __restrict__ AV,
    const float4* __restrict__ AE,
    const float* __restrict__ X, const float* __restrict__ Z,
    const float* __restrict__ W1, const float* __restrict__ Wf1,
    const float* __restrict__ g1, const float* __restrict__ be1,
    const float* __restrict__ Wf2, const float* __restrict__ g2,
    const float* __restrict__ be2, const float* __restrict__ W2,
    const float* __restrict__ p1, const float* __restrict__ p2,
    const float* __restrict__ p3)
{
    int b = blockIdx.x;
    // piggyback clear of g_lcnt (blocks 0..255; consumed only in k_all)
    int ci = b * 256 + threadIdx.x;
    if (ci < Nn * MDV) g_lcnt[ci] = 0;

    if (b < NFRONT) {
        if (b < 64) {
            front_dot(b, Z, p1);
        } else if (b < 320) {
            front_gemm16((b - 64) * 16, Z, Wf2, g_Z2F2, 32, 16, 0, 1, g2, be2, g_s3, p3); // F2 + s3 seed
        } else if (b < 576) {
            front_gemm16((b - 320) * 16, Z, W2, g_HWe, 16, 0, 1, 0, 0, 0, 0, 0);         // HW2 = relu(Z)@W2
        } else if (b < 1600) {
            front_gemm128((b - 576) * 2, X, W1, g_HWn, 128, 0, 0, 0, 0, 0, 0);           // HW1
        } else {
            front_gemm128((b - 1600) * 2, X, Wf1, g_X1F1, 256, 128, 1, g1, be1, g_s2, p2); // F1 + s2 seed
        }
        return;
    }
    // scan role: 8 independent coalesced float4 loads per thread (MLP=8)
    int sb = b - NFRONT;
    int base0 = sb * 2048 + threadIdx.x;
    float4 v[8];
    #pragma unroll
    for (int k = 0; k < 8; k++)
        v[k] = __ldcs(scan_addr(base0 + k * 256, T, AV, AE));
    #pragma unroll
    for (int k = 0; k < 8; k++)
        scan_elem(base0 + k * 256, v[k]);
}

// ---------------- persistent phase bodies ----------------
__device__ __forceinline__ int find_entry(int row, int col) {
    int cnt = g_vcnt[row]; if (cnt > MDV) cnt = MDV;
    for (int s = 0; s < cnt; s++)
        if (g_vcol[row * MDV + s] == col) return row * MDV + s;
    return -1;
}

__device__ void ph_map() {
    for (int e = blockIdx.x * NT + threadIdx.x; e < Ee; e += GSTRIDE) {
        int a = g_en[2 * e], b = g_en[2 * e + 1];
        if (a > b) { int t = a; a = b; b = t; g_en[2 * e] = a; g_en[2 * e + 1] = b; }
        if (a == b) continue;
        int id0 = find_entry(a, b);
        if (id0 >= 0) {
            int slot = atomicAdd(&g_lcnt[id0], 1);
            if (slot < LMAX) g_elist[id0 * LMAX + slot] = e;
        }
        int id1 = find_entry(b, a);
        if (id1 >= 0) {
            int slot = atomicAdd(&g_lcnt[id1], 1);
            if (slot < LMAX) g_elist[id1 * LMAX + slot] = e;
        }
    }
}

__device__ void ph_colmax_seed() {
    for (int f = blockIdx.x * NT + threadIdx.x; f < Ee; f += GSTRIDE) {
        unsigned v = f2ord(g_ediag[f]);
        g_colmaxA[f] = v;
        g_colmaxB[f] = v;
    }
}

// persistent 128-col GEMM, 8 subgroups of 128 threads
__device__ void ph_gemm128(const float* __restrict__ A, int lda, int K,
                           const float* __restrict__ B, float* __restrict__ out,
                           float* shAs, int R) {
    int sub = threadIdx.x >> 7;
    int c = threadIdx.x & 127;
    float* As = shAs + sub * 256;
    const int ngrp = NB * 8;
    int trips = (R + ngrp - 1) / ngrp;
    for (int t = 0; t < trips; t++) {
        int r = t * ngrp + blockIdx.x * 8 + sub;
        bool act = r < R;
        __syncthreads();
        if (act) for (int k = c; k < K; k += 128) As[k] = A[r * lda + k];
        __syncthreads();
        float acc = 0.f;
        if (act) {
            #pragma unroll 8
            for (int k = 0; k < K; k++) acc += As[k] * B[k * 128 + c];
            out[r * 128 + c] = acc;
        }
    }
}

// persistent 16-col GEMM, 64 row-groups
__device__ void ph_gemm16(const float* __restrict__ A, int lda, int K,
                          const float* __restrict__ B, float* __restrict__ out,
                          float* shAsf, int R) {
    float (*As)[32] = (float (*)[32])shAsf;
    int rg = threadIdx.x >> 4, c = threadIdx.x & 15;
    const int nrows = NB * 64;
    int trips = (R + nrows - 1) / nrows;
    for (int t = 0; t < trips; t++) {
        int r = t * nrows + blockIdx.x * 64 + rg;
        bool act = r < R;
        __syncthreads();
        if (act) for (int k = c; k < K; k += 16) As[rg][k] = A[r * lda + k];
        __syncthreads();
        if (act) {
            float acc = 0.f;
            #pragma unroll 8
            for (int k = 0; k < K; k++) acc += As[rg][k] * B[k * 16 + c];
            out[r * 16 + c] = acc;
        }
    }
}

__device__ void ph_gather_node(const float* __restrict__ sgate,
                               const float* __restrict__ bias, float* __restrict__ out,
                               int ldc, int relu,
                               float* __restrict__ sacc, const float* __restrict__ pvec) {
    int lane = threadIdx.x & 31;
    for (int v = blockIdx.x * NT + threadIdx.x; v < Nn * 128; v += GSTRIDE) {
        int i = v >> 7, c = v & 127;
        float acc = bias[c] + g_vdiag[i] * g_HWn[i * 128 + c];
        int cnt = g_vcnt[i]; if (cnt > MDV) cnt = MDV;
        for (int s = 0; s < cnt; s++) {
            int id = i * MDV + s;
            int lc = g_lcnt[id]; if (lc > LMAX) lc = LMAX;
            float ms = 0.f;
            for (int l = 0; l < lc; l++) ms += sgate[g_elist[id * LMAX + l]];
            acc += ms * g_vvalp[id] * g_HWn[g_vcol[id] * 128 + c];
        }
        if (relu) acc = fmaxf(acc, 0.f);
        out[i * ldc + c] = acc;
        if (sacc) {
            float con = acc * pvec[c];
            #pragma unroll
            for (int o = 16; o > 0; o >>= 1) con += __shfl_xor_sync(0xffffffffu, con, o);
            if (lane == 0) atomicAdd(&sacc[i], con);
        }
    }
}

__device__ void ph_entries(const float* __restrict__ sgate, unsigned* __restrict__ colmax) {
    for (int e = blockIdx.x * NT + threadIdx.x; e < Ee; e += GSTRIDE) {
        int a0 = g_en[2 * e], a1 = g_en[2 * e + 1];
        float sa0 = sgate[a0], sa1 = sgate[a1];
        int cnt = g_ecnt2[e]; if (cnt > MDE) cnt = MDE;
        for (int s = 0; s < cnt; s++) {
            int id = e * MDE + s;
            int f = g_ecol[id];
            int b0 = g_en[2 * f], b1 = g_en[2 * f + 1];
            float m = sa0 * ((float)(a0 == b0) + (float)(a0 == b1))
                    + sa1 * ((float)(a1 == b0) + (float)(a1 == b1));
            float av = m * g_evalp[id];
            g_aval[id] = av;
            atomicMax(&colmax[f], f2ord(av));
        }
    }
}

__device__ void ph_gather_edge(const unsigned* __restrict__ colmax,
                               const float* __restrict__ bias, float* __restrict__ out,
                               int ldc, int relu,
                               float* __restrict__ sacc, const float* __restrict__ pvec) {
    int lane = threadIdx.x & 31;
    for (int v = blockIdx.x * NT + threadIdx.x; v < Ee * 16; v += GSTRIDE) {
        int e = v >> 4, c = v & 15;
        float acc = bias[c] + g_ediag[e] * (1.f / ord2f(colmax[e])) * g_HWe[e * 16 + c];
        int cnt = g_ecnt2[e]; if (cnt > MDE) cnt = MDE;
        for (int s = 0; s < cnt; s++) {
            int id = e * MDE + s;
            int f = g_ecol[id];
            acc += g_aval[id] * (1.f / ord2f(colmax[f])) * g_HWe[f * 16 + c];
        }
        if (relu) acc = fmaxf(acc, 0.f);
        out[e * ldc + c] = acc;
        if (sacc) {
            float con = acc * pvec[c];
            #pragma unroll
            for (int o = 8; o > 0; o >>= 1) con += __shfl_xor_sync(0xffffffffu, con, o, 16);
            if ((lane & 15) == 0) atomicAdd(&sacc[e], con);
        }
    }
}

// ---------------- persistent kernel: 8 phases, 7 barriers ----------------
__global__ void __launch_bounds__(NT) k_all(
    const float* __restrict__ p2, const float* __restrict__ p3,
    const float* __restrict__ p4, const float* __restrict__ p5,
    const float* __restrict__ b1, const float* __restrict__ b2,
    const float* __restrict__ b3, const float* __restrict__ b4,
    const float* __restrict__ b5,
    const float* __restrict__ W3, const float* __restrict__ W4,
    const float* __restrict__ W5,
    float* __restrict__ out)
{
    __shared__ float shAs[2048];

    // P2: map + colmax seeds
    ph_map();
    ph_colmax_seed();
    gbar();
    // P3: gather X1 (msum inline from s1) + accumulate s2
    ph_gather_node(g_s1, b1, g_X1F1, 256, 1, g_s2, p2);
    gbar();
    // P4: gc2 entries + HW3
    ph_entries(g_s2, g_colmaxA);
    ph_gemm128(g_X1F1, 256, 256, W3, g_HWn, shAs, Nn);
    gbar();
    // P5: gather Z2 + accumulate s3
    ph_gather_edge(g_colmaxA, b2, g_Z2F2, 32, 1, g_s3, p3);
    gbar();
    // P6: gather X3 + accumulate s4 + HW4
    ph_gather_node(g_s3, b3, g_X3, 128, 1, g_s4, p4);
    ph_gemm16(g_Z2F2, 32, 32, W4, g_HWe, shAs, Ee);
    gbar();
    // P7: gc4 entries + HW5
    ph_entries(g_s4, g_colmaxB);
    ph_gemm128(g_X3, 128, 128, W5, g_HWn, shAs, Nn);
    gbar();
    // P8: gather Z4 + accumulate s5
    ph_gather_edge(g_colmaxB, b4, g_Z4, 16, 1, g_s5, p5);
    gbar();
    // P9: gather out (no relu)
    ph_gather_node(g_s5, b5, out, 128, 0, 0, 0);
}

// ---------------- host launcher ----------------
extern "C" void kernel_launch(void* const* d_in, const int* in_sizes, int n_in,
                              void* d_out, int out_size) {
    (void)in_sizes; (void)n_in; (void)out_size;
    const float* X     = (const float*)d_in[0];
    const float* Z     = (const float*)d_in[1];
    const float* adj_e = (const float*)d_in[2];
    const float* adj_v = (const float*)d_in[3];
    const float* T     = (const float*)d_in[4];

    k_clear<<<(Ee + 255) / 256, 256>>>();
    k_scanfront<<<NGRID, 256>>>(
        (const float4*)T, (const float4*)adj_v, (const float4*)adj_e,
        X, Z,
        (const float*)d_in[5],   // W1
        (const float*)d_in[8],   // Wf1
        (const float*)d_in[9],   // g1
        (const float*)d_in[10],  // be1
        (const float*)d_in[14],  // Wf2
        (const float*)d_in[15],  // g2
        (const float*)d_in[16],  // be2
        (const float*)d_in[11],  // W2
        (const float*)d_in[6],   // p1
        (const float*)d_in[12],  // p2
        (const float*)d_in[18]); // p3
    k_all<<<NB, NT>>>(
        (const float*)d_in[12],  // p2
        (const float*)d_in[18],  // p3
        (const float*)d_in[21],  // p4
        (const float*)d_in[24],  // p5
        (const float*)d_in[7],   // b1
        (const float*)d_in[13],  // b2
        (const float*)d_in[19],  // b3
        (const float*)d_in[22],  // b4
        (const float*)d_in[25],  // b5
        (const float*)d_in[17],  // W3
        (const float*)d_in[20],  // W4
        (const float*)d_in[23],  // W5
        (float*)d_out);
}